// round 17
// baseline (speedup 1.0000x reference)
#include <cuda_runtime.h>
#include <cuda_fp16.h>
#include <math.h>
#include <stdint.h>

// ---------------------------------------------------------------------------
// FormationOptimizer: fully-connected GNN, N=512, 3 message-passing rounds.
// Edge layer0 factorized: A[i] + B[j] + dist*wd (fp32). Edge MLP GEMMs on
// tensor cores via mma.sync.m16n8k16 fp16 with ldmatrix fragment loads.
// 1 CTA/SM, 8 FULLY INDEPENDENT single-warp pipelines (item = 16 edges);
// no inter-warp barriers, only __syncwarp. W1(k<64)+W2 in registers.
// ---------------------------------------------------------------------------

#define NN 512
#define FD 64
#define H0D 128

__device__ float g_NF[NN * FD];
__device__ float g_DIST[NN * NN];
__device__ float g_A[NN * H0D];      // nf @ ew0[0:64]        [node][k]
__device__ float g_B[NN * H0D];      // nf @ ew0[64:128]+eb0  [node][k]
__device__ float g_AGG[NN * 32];

__device__ __forceinline__ uint32_t pack_h2(float lo, float hi) {
    __half2 h = __floats2half2_rn(lo, hi);
    return *(uint32_t*)&h;
}
__device__ __forceinline__ uint32_t hmax2z(uint32_t x) {
    uint32_t r;
    asm("max.f16x2 %0, %1, %2;" : "=r"(r) : "r"(x), "r"(0u));
    return r;
}
__device__ __forceinline__ void mma16(float* c, const uint32_t* a, const uint32_t* b) {
    asm volatile(
        "mma.sync.aligned.m16n8k16.row.col.f32.f16.f16.f32 "
        "{%0,%1,%2,%3}, {%4,%5,%6,%7}, {%8,%9}, {%0,%1,%2,%3};"
        : "+f"(c[0]), "+f"(c[1]), "+f"(c[2]), "+f"(c[3])
        : "r"(a[0]), "r"(a[1]), "r"(a[2]), "r"(a[3]), "r"(b[0]), "r"(b[1]));
}
__device__ __forceinline__ void ldsm4(uint32_t* r, uint32_t saddr) {
    asm volatile(
        "ldmatrix.sync.aligned.m8n8.x4.shared.b16 {%0,%1,%2,%3}, [%4];"
        : "=r"(r[0]), "=r"(r[1]), "=r"(r[2]), "=r"(r[3]) : "r"(saddr));
}

// ---------------------------------------------------------------------------
__global__ void k_init_nf(const float* __restrict__ states,
                          const float* __restrict__ obj) {
    int idx = blockIdx.x * 256 + threadIdx.x;
    int i = idx >> 6, c = idx & 63;
    g_NF[idx] = (c < 6) ? states[i * 6 + c] : obj[c - 6];
}

__global__ void k_init_dist(const float* __restrict__ states) {
    int i = blockIdx.x, t = threadIdx.x;
    float px = states[i * 6 + 0], py = states[i * 6 + 1], pz = states[i * 6 + 2];
    for (int j = t; j < NN; j += blockDim.x) {
        float dx = states[j * 6 + 0] - px;
        float dy = states[j * 6 + 1] - py;
        float dz = states[j * 6 + 2] - pz;
        g_DIST[i * NN + j] = sqrtf(dx * dx + dy * dy + dz * dz);
    }
}

// ---------------------------------------------------------------------------
// k_proj: A/B for iteration 0, zero g_AGG.
// ---------------------------------------------------------------------------
#define PROJ_SMEM (16384 + 512)
__global__ void __launch_bounds__(256) k_proj(const float* __restrict__ ew0,
                                              const float* __restrict__ eb0) {
    extern __shared__ float sm[];
    float* sE = sm;
    float* snf = sm + 16384;
    const int t = threadIdx.x;
    const int nb8 = blockIdx.x * 8;

    for (int q = 0; q < 16; q++)
        *(float4*)(sE + q * 1024 + t * 4) = *(const float4*)(ew0 + q * 1024 + t * 4);
    for (int q = 0; q < 2; q++)
        snf[q * 256 + t] = g_NF[nb8 * 64 + q * 256 + t];
    g_AGG[blockIdx.x * 256 + t] = 0.f;
    __syncthreads();

    const int nd = t >> 5;
    const int k4 = (t & 31) * 4;
    float4 a = make_float4(0.f, 0.f, 0.f, 0.f);
    float4 b = make_float4(0.f, 0.f, 0.f, 0.f);
#pragma unroll 4
    for (int c = 0; c < 64; c++) {
        float v = snf[nd * 64 + c];
        float4 wa = *(const float4*)(sE + c * 128 + k4);
        float4 wb = *(const float4*)(sE + (64 + c) * 128 + k4);
        a.x = fmaf(v, wa.x, a.x); a.y = fmaf(v, wa.y, a.y);
        a.z = fmaf(v, wa.z, a.z); a.w = fmaf(v, wa.w, a.w);
        b.x = fmaf(v, wb.x, b.x); b.y = fmaf(v, wb.y, b.y);
        b.z = fmaf(v, wb.z, b.z); b.w = fmaf(v, wb.w, b.w);
    }
    float4 e = *(const float4*)(eb0 + k4);
    b.x += e.x; b.y += e.y; b.z += e.z; b.w += e.w;
    *(float4*)(g_A + (nb8 + nd) * 128 + k4) = a;
    *(float4*)(g_B + (nb8 + nd) * 128 + k4) = b;
}

// ---------------------------------------------------------------------------
// k_edge: persistent fp16 mma, grid=148 (1 CTA/SM), 256 threads.
// 8 independent single-warp pipelines; item = (j, 16-sender tile).
// smem words: W1t[64][68] | W2t[32][36] | 8w x H0[16][68] | 8w x H1[16][36]
// ---------------------------------------------------------------------------
#define S_W1T 0
#define S_W2T 4352
#define S_H0  5504
#define S_H1  14208
#define E_SMEMW 18816    // words -> 75264 bytes

#define NITEM_W 16384
#define EGRID 148
#define NWARP 8
#define WPIPE (EGRID * NWARP)

// H0[e][k] = relu(A[i][k] + B[j][k] + d*wd[k]); full warp builds 16 rows.
__device__ __forceinline__ void compute_H0(uint32_t* __restrict__ dstbuf,
                                           int j, int ibase, int lane,
                                           const float* __restrict__ ew0)
{
    const float4 wv = __ldg((const float4*)(ew0 + 128 * H0D) + lane);
    float dl = 0.f;
    if (lane < 16) dl = __ldg(g_DIST + j * NN + ibase + lane);
    const float4 bv = __ldg((const float4*)(g_B + j * H0D) + lane);
    uint32_t* dst = dstbuf + 2 * lane;
#pragma unroll
    for (int e = 0; e < 16; e++) {
        float d = __shfl_sync(0xffffffffu, dl, e);
        float4 av = __ldg((const float4*)(g_A + (ibase + e) * H0D) + lane);
        float f0 = fmaf(d, wv.x, av.x + bv.x);
        float f1 = fmaf(d, wv.y, av.y + bv.y);
        float f2 = fmaf(d, wv.z, av.z + bv.z);
        float f3 = fmaf(d, wv.w, av.w + bv.w);
        uint2 u;
        u.x = hmax2z(pack_h2(f0, f1));
        u.y = hmax2z(pack_h2(f2, f3));
        *(uint2*)(dst + e * 68) = u;
    }
}

__global__ void __launch_bounds__(256, 1) k_edge(
    const float* __restrict__ ew0, const float* __restrict__ ew1,
    const float* __restrict__ eb1, const float* __restrict__ ew2,
    const float* __restrict__ eb2)
{
    extern __shared__ uint32_t smw[];
    uint32_t* sW1tw = smw + S_W1T;
    uint32_t* sW2tw = smw + S_W2T;
    const uint32_t sb = (uint32_t)__cvta_generic_to_shared(smw);

    const int t = threadIdx.x;
    const int lane = t & 31;
    const int w = t >> 5;
    const int ar = lane >> 2;
    const int ac = lane & 3;

    uint32_t* sH0w = smw + S_H0 + w * (16 * 68);
    uint32_t* sH1w = smw + S_H1 + w * (16 * 36);

    // ---- stage weights (transposed, fp16 pairs) once per CTA ----
    for (int idx = t; idx < 4096; idx += 256) {
        int n = idx >> 6, wk = idx & 63;
        sW1tw[n * 68 + wk] = pack_h2(__ldg(ew1 + (2 * wk) * 64 + n),
                                     __ldg(ew1 + (2 * wk + 1) * 64 + n));
    }
    for (int idx = t; idx < 1024; idx += 256) {
        int m = idx >> 5, wk = idx & 31;
        sW2tw[m * 36 + wk] = pack_h2(__ldg(ew2 + (2 * wk) * 32 + m),
                                     __ldg(ew2 + (2 * wk + 1) * 32 + m));
    }

    // ldmatrix per-lane offsets (word units)
    const int lrowA = ((lane >> 3) & 1) * 8 + (lane & 7);
    const int lcolA = (lane >> 4) * 4;
    const int lrowB = ((lane >> 4) & 1) * 8 + (lane & 7);
    const int lcolB = ((lane >> 3) & 1) * 4;

    // biases: full n=64 (GEMM1), full m=32 (GEMM2)
    float e1b[8][2];
#pragma unroll
    for (int ni = 0; ni < 8; ni++) {
        e1b[ni][0] = __ldg(eb1 + ni * 8 + 2 * ac);
        e1b[ni][1] = __ldg(eb1 + ni * 8 + 2 * ac + 1);
    }
    float e2b[4][2];
#pragma unroll
    for (int ni = 0; ni < 4; ni++) {
        e2b[ni][0] = __ldg(eb2 + ni * 8 + 2 * ac);
        e2b[ni][1] = __ldg(eb2 + ni * 8 + 2 * ac + 1);
    }

    // ldmatrix base addresses (bytes)
    const uint32_t aH0 = sb + (S_H0 + w * 16 * 68 + lrowA * 68 + lcolA) * 4;
    uint32_t aW1[4];
#pragma unroll
    for (int b = 0; b < 4; b++)
        aW1[b] = sb + (S_W1T + (b * 16 + lrowB) * 68 + lcolB) * 4;
    const uint32_t aH1 = sb + (S_H1 + w * 16 * 36 + lrowA * 36 + lcolA) * 4;
    const uint32_t aW2_0 = sb + (S_W2T + lrowB * 36 + lcolB) * 4;
    const uint32_t aW2_1 = aW2_0 + 16 * 36 * 4;

    __syncthreads();   // weights staged (only CTA-wide sync)

    // ---- register-resident fragments: W1 ks 0..3 full-n (64), W2 all (32) ---
    uint32_t w1f[4][16];
#pragma unroll
    for (int ks = 0; ks < 4; ks++)
#pragma unroll
        for (int b = 0; b < 4; b++)
            ldsm4(&w1f[ks][b * 4], aW1[b] + ks * 32);
    uint32_t w2f[4][8];
#pragma unroll
    for (int ks = 0; ks < 4; ks++) {
        ldsm4(&w2f[ks][0], aW2_0 + ks * 32);
        ldsm4(&w2f[ks][4], aW2_1 + ks * 32);
    }

    int s = blockIdx.x * NWARP + w;      // item index for this warp pipeline
    while (s < NITEM_W) {
        const int j = s >> 5;
        const int ibase = (s & 31) * 16;

        compute_H0(sH0w, j, ibase, lane, ew0);
        __syncwarp();

        // ================ GEMM1: H1 = relu(H0 @ W1 + b1), 16e x 64n ========
        {
            float acc[8][4];
#pragma unroll
            for (int ni = 0; ni < 8; ni++) {
                acc[ni][0] = e1b[ni][0];
                acc[ni][1] = e1b[ni][1];
                acc[ni][2] = e1b[ni][0];
                acc[ni][3] = e1b[ni][1];
            }
#pragma unroll
            for (int ks = 0; ks < 8; ks++) {
                uint32_t a[4];
                ldsm4(a, aH0 + ks * 32);
                uint32_t bb[16];
                const uint32_t* bf;
                if (ks < 4) {
                    bf = w1f[ks];
                } else {
#pragma unroll
                    for (int b = 0; b < 4; b++)
                        ldsm4(&bb[b * 4], aW1[b] + ks * 32);
                    bf = bb;
                }
#pragma unroll
                for (int ni = 0; ni < 8; ni++)
                    mma16(acc[ni], a, &bf[(ni >> 1) * 4 + (ni & 1) * 2]);
            }
            // epilogue: pack -> relu(f16x2) -> H1
#pragma unroll
            for (int ni = 0; ni < 8; ni++) {
                const int wc = ni * 4 + ac;
                sH1w[ar * 36 + wc] = hmax2z(pack_h2(acc[ni][0], acc[ni][1]));
                sH1w[(ar + 8) * 36 + wc] = hmax2z(pack_h2(acc[ni][2], acc[ni][3]));
            }
        }
        __syncwarp();

        // ================ GEMM2 + masked reduction, 16e x 32m ==============
        {
            float acc[4][4];
#pragma unroll
            for (int ni = 0; ni < 4; ni++) {
                acc[ni][0] = e2b[ni][0];
                acc[ni][1] = e2b[ni][1];
                acc[ni][2] = e2b[ni][0];
                acc[ni][3] = e2b[ni][1];
            }
#pragma unroll
            for (int ks = 0; ks < 4; ks++) {
                uint32_t a[4];
                ldsm4(a, aH1 + ks * 32);
#pragma unroll
                for (int ni = 0; ni < 4; ni++)
                    mma16(acc[ni], a, &w2f[ks][(ni >> 1) * 4 + (ni & 1) * 2]);
            }
            const int i0 = ibase + ar;
            const bool k0 = (i0 != j);
            const bool k1 = (i0 + 8 != j);
            float s0[4], s1[4];
#pragma unroll
            for (int ni = 0; ni < 4; ni++) {
                float a0 = k0 ? fmaxf(acc[ni][0], 0.f) : 0.f;
                float a1 = k0 ? fmaxf(acc[ni][1], 0.f) : 0.f;
                float a2 = k1 ? fmaxf(acc[ni][2], 0.f) : 0.f;
                float a3 = k1 ? fmaxf(acc[ni][3], 0.f) : 0.f;
                s0[ni] = a0 + a2;
                s1[ni] = a1 + a3;
            }
#pragma unroll
            for (int off = 4; off <= 16; off <<= 1) {
#pragma unroll
                for (int ni = 0; ni < 4; ni++) {
                    s0[ni] += __shfl_xor_sync(0xffffffffu, s0[ni], off);
                    s1[ni] += __shfl_xor_sync(0xffffffffu, s1[ni], off);
                }
            }
            if (lane < 4) {
                float* dst = g_AGG + j * 32 + 2 * ac;
#pragma unroll
                for (int ni = 0; ni < 4; ni++) {
                    atomicAdd(dst + ni * 8, s0[ni]);
                    atomicAdd(dst + ni * 8 + 1, s1[ni]);
                }
            }
        }
        s += WPIPE;
    }
}

// ---------------------------------------------------------------------------
// k_node: 256 CTAs x 2 nodes, 256 threads. Node MLP + residual, fused
// projection (A/B for next edge pass), zero g_AGG.
// ---------------------------------------------------------------------------
__global__ void __launch_bounds__(256) k_node(
    const float* __restrict__ nw0, const float* __restrict__ nb0,
    const float* __restrict__ nw1, const float* __restrict__ nb1,
    const float* __restrict__ nw2, const float* __restrict__ nb2,
    const float* __restrict__ nwo, const float* __restrict__ nbo,
    const float* __restrict__ ew0, const float* __restrict__ eb0)
{
    __shared__ float sy[2 * 96], sh0[2 * 128], sh1[2 * 64], sh2[2 * 32], sNF[2 * 64];
    const int t = threadIdx.x;
    const int nb2_ = blockIdx.x * 2;

    if (t < 192) {
        int nd = t / 96, c = t % 96;
        sy[t] = (c < 64) ? g_NF[(nb2_ + nd) * 64 + c]
                         : g_AGG[(nb2_ + nd) * 32 + (c - 64)];
    }
    __syncthreads();
    if (t < 64) g_AGG[blockIdx.x * 64 + t] = 0.f;

    const int nd = t >> 7;
    const int o = t & 127;
    // layer 0: 96 -> 128
    {
        float acc = __ldg(nb0 + o);
#pragma unroll 8
        for (int c = 0; c < 96; c++)
            acc = fmaf(sy[nd * 96 + c], __ldg(nw0 + c * 128 + o), acc);
        sh0[nd * 128 + o] = fmaxf(acc, 0.f);
    }
    __syncthreads();
    // layer 1: 128 -> 64
    if (t < 128) {
        const int n1 = t >> 6, o1 = t & 63;
        float acc = __ldg(nb1 + o1);
#pragma unroll 8
        for (int c = 0; c < 128; c++)
            acc = fmaf(sh0[n1 * 128 + c], __ldg(nw1 + c * 64 + o1), acc);
        sh1[n1 * 64 + o1] = fmaxf(acc, 0.f);
    }
    __syncthreads();
    // layer 2: 64 -> 32
    if (t < 64) {
        const int n2 = t >> 5, o2 = t & 31;
        float acc = __ldg(nb2 + o2);
#pragma unroll 8
        for (int c = 0; c < 64; c++)
            acc = fmaf(sh1[n2 * 64 + c], __ldg(nw2 + c * 32 + o2), acc);
        sh2[n2 * 32 + o2] = fmaxf(acc, 0.f);
    }
    __syncthreads();
    // output: 32 -> 64, residual
    if (t < 128) {
        const int n3 = t >> 6, o3 = t & 63;
        float acc = __ldg(nbo + o3);
#pragma unroll 8
        for (int c = 0; c < 32; c++)
            acc = fmaf(sh2[n3 * 32 + c], __ldg(nwo + c * 64 + o3), acc);
        float y = sy[n3 * 96 + o3] + acc;
        g_NF[(nb2_ + n3) * 64 + o3] = y;
        sNF[n3 * 64 + o3] = y;
    }
    __syncthreads();
    // fused projection: A = nf@ew0[0:64], B = nf@ew0[64:128]+eb0
    {
        float a = 0.f, b = 0.f;
#pragma unroll 8
        for (int c = 0; c < 64; c++) {
            float v = sNF[nd * 64 + c];
            a = fmaf(v, __ldg(ew0 + c * 128 + o), a);
            b = fmaf(v, __ldg(ew0 + (64 + c) * 128 + o), b);
        }
        b += __ldg(eb0 + o);
        const int node = nb2_ + nd;
        g_A[node * 128 + o] = a;
        g_B[node * 128 + o] = b;
    }
}

// ---------------------------------------------------------------------------
__global__ void k_read(const float* __restrict__ rw, const float* __restrict__ rb,
                       float* __restrict__ out)
{
    int jn = blockIdx.x * blockDim.x + threadIdx.x;
    if (jn >= NN) return;
    float a0 = rb[0], a1 = rb[1], a2 = rb[2];
#pragma unroll
    for (int c = 0; c < 64; c++) {
        float v = g_NF[jn * FD + c];
        a0 = fmaf(v, rw[c * 3 + 0], a0);
        a1 = fmaf(v, rw[c * 3 + 1], a1);
        a2 = fmaf(v, rw[c * 3 + 2], a2);
    }
    out[jn * 3 + 0] = a0;
    out[jn * 3 + 1] = a1;
    out[jn * 3 + 2] = a2;
}

// ---------------------------------------------------------------------------
extern "C" void kernel_launch(void* const* d_in, const int* in_sizes, int n_in,
                              void* d_out, int out_size)
{
    const float* states = (const float*)d_in[0];
    const float* obj    = (const float*)d_in[1];
    const float* ew0 = (const float*)d_in[2];
    const float* eb0 = (const float*)d_in[3];
    const float* ew1 = (const float*)d_in[4];
    const float* eb1 = (const float*)d_in[5];
    const float* ew2 = (const float*)d_in[6];
    const float* eb2 = (const float*)d_in[7];
    const float* nw0 = (const float*)d_in[8];
    const float* nb0 = (const float*)d_in[9];
    const float* nw1 = (const float*)d_in[10];
    const float* nb1 = (const float*)d_in[11];
    const float* nw2 = (const float*)d_in[12];
    const float* nb2 = (const float*)d_in[13];
    const float* nwo = (const float*)d_in[14];
    const float* nbo = (const float*)d_in[15];
    const float* rw  = (const float*)d_in[16];
    const float* rb  = (const float*)d_in[17];
    float* out = (float*)d_out;

    cudaFuncSetAttribute(k_edge, cudaFuncAttributeMaxDynamicSharedMemorySize,
                         E_SMEMW * (int)sizeof(uint32_t));
    cudaFuncSetAttribute(k_proj, cudaFuncAttributeMaxDynamicSharedMemorySize,
                         PROJ_SMEM * (int)sizeof(float));

    // launch order keeps the 2nd k_edge at index 5 (ncu -s 5 -c 1 capture slot)
    k_init_nf<<<128, 256>>>(states, obj);
    k_init_dist<<<NN, 256>>>(states);
    k_proj<<<64, 256, PROJ_SMEM * (int)sizeof(float)>>>(ew0, eb0);
    for (int it = 0; it < 3; it++) {
        k_edge<<<EGRID, 256, E_SMEMW * (int)sizeof(uint32_t)>>>(ew0, ew1, eb1, ew2, eb2);
        k_node<<<256, 256>>>(nw0, nb0, nw1, nb1, nw2, nb2, nwo, nbo, ew0, eb0);
    }
    k_read<<<4, 128>>>(rw, rb, out);
}